// round 2
// baseline (speedup 1.0000x reference)
#include <cuda_runtime.h>

#define HW      (128 * 128)     // rays
#define KPRIM   32
#define MM      16
#define NSTEPS  64
#define DTSTEP  (1.0f / 64.0f)

// Repacked template: [k][z][y][x][c], c fastest (float4 per voxel). 2 MB.
__device__ float g_tpl[KPRIM * MM * MM * MM * 4];

// ---------------------------------------------------------------------------
// Repack kernel: template[b=0][k][c][z][y][x]  ->  g_tpl[k][z][y][x][c]
// ---------------------------------------------------------------------------
__global__ void repack_kernel(const float* __restrict__ tpl) {
    int i = blockIdx.x * blockDim.x + threadIdx.x;
    const int N = KPRIM * 4 * MM * MM * MM;  // 524288
    if (i >= N) return;
    int x = i & 15;  int t = i >> 4;
    int y = t & 15;  t >>= 4;
    int z = t & 15;  t >>= 4;
    int c = t & 3;   int k = t >> 2;
    g_tpl[((((k * 16 + z) * 16 + y) * 16 + x) << 2) + c] = tpl[i];
}

// ---------------------------------------------------------------------------
// March kernel: one warp per ray, one lane per primitive (K == 32).
// ---------------------------------------------------------------------------
__global__ void __launch_bounds__(256) march_kernel(
    const float* __restrict__ raypos,
    const float* __restrict__ raydir,
    const float* __restrict__ tminmax,
    const float* __restrict__ primpos,
    const float* __restrict__ primrot,
    const float* __restrict__ primscale,
    float* __restrict__ out)
{
    const unsigned FULL = 0xffffffffu;
    int gwarp = (blockIdx.x * blockDim.x + threadIdx.x) >> 5;
    int lane  = threadIdx.x & 31;
    if (gwarp >= HW) return;
    const int r = gwarp;   // ray index

    // ---- per-lane primitive constants (lane == prim index) ----
    float px = primpos[lane * 3 + 0];
    float py = primpos[lane * 3 + 1];
    float pz = primpos[lane * 3 + 2];
    float s0 = primscale[lane * 3 + 0];
    float s1 = primscale[lane * 3 + 1];
    float s2 = primscale[lane * 3 + 2];
    const float* Rm = primrot + lane * 9;
    // fold scale into rotation rows: y_i = (R[i]·xl) * s_i
    float r00 = Rm[0] * s0, r01 = Rm[1] * s0, r02 = Rm[2] * s0;
    float r10 = Rm[3] * s1, r11 = Rm[4] * s1, r12 = Rm[5] * s1;
    float r20 = Rm[6] * s2, r21 = Rm[7] * s2, r22 = Rm[8] * s2;

    // ---- per-ray data (broadcast load: all lanes same address) ----
    float ox = raypos[r * 3 + 0], oy = raypos[r * 3 + 1], oz = raypos[r * 3 + 2];
    float dx = raydir[r * 3 + 0], dy = raydir[r * 3 + 1], dz = raydir[r * 3 + 2];
    float tmin = tminmax[r * 2 + 0];
    float tmax = tminmax[r * 2 + 1];

    const float4* tp4 = reinterpret_cast<const float4*>(g_tpl) + lane * (MM * MM * MM);

    float rgbx = 0.f, rgby = 0.f, rgbz = 0.f, alpha = 0.f;

    #pragma unroll 1
    for (int i = 0; i < NSTEPS; i++) {
        float t = fmaf((float)i, DTSTEP, tmin);
        if (t >= tmax) break;  // exact: valid=0 => contrib=0 for all later steps

        // world pos -> primitive-local (scaled) coords
        float wx = fmaf(t, dx, ox) - px;
        float wy = fmaf(t, dy, oy) - py;
        float wz = fmaf(t, dz, oz) - pz;
        float y0 = fmaf(r00, wx, fmaf(r01, wy, r02 * wz));  // -> z axis of grid
        float y1 = fmaf(r10, wx, fmaf(r11, wy, r12 * wz));  // -> y axis
        float y2 = fmaf(r20, wx, fmaf(r21, wy, r22 * wz));  // -> x axis

        bool inside = (fabsf(y0) <= 1.f) & (fabsf(y1) <= 1.f) & (fabsf(y2) <= 1.f);

        unsigned act = __ballot_sync(FULL, inside);
        if (act == 0u) continue;  // no prim sampled -> contrib exactly 0

        float4 samp = make_float4(0.f, 0.f, 0.f, 0.f);
        if (inside) {
            // trilinear fetch: g = (y+1) * 0.5 * (M-1)
            float gz = fmaf(y0, 7.5f, 7.5f);
            float gy = fmaf(y1, 7.5f, 7.5f);
            float gx = fmaf(y2, 7.5f, 7.5f);
            int iz = min(max((int)floorf(gz), 0), 14);
            int iy = min(max((int)floorf(gy), 0), 14);
            int ix = min(max((int)floorf(gx), 0), 14);
            float fz = fminf(fmaxf(gz - (float)iz, 0.f), 1.f);
            float fy = fminf(fmaxf(gy - (float)iy, 0.f), 1.f);
            float fx = fminf(fmaxf(gx - (float)ix, 0.f), 1.f);

            const float4* base = tp4 + ((iz * 16 + iy) * 16 + ix);
            float4 c000 = base[0],    c001 = base[1];
            float4 c010 = base[16],   c011 = base[17];
            float4 c100 = base[256],  c101 = base[257];
            float4 c110 = base[272],  c111 = base[273];

            float ez = 1.f - fz, ey = 1.f - fy, ex = 1.f - fx;
            float a00 = ez * ey, a01 = ez * fy, a10 = fz * ey, a11 = fz * fy;
            float w000 = a00 * ex, w001 = a00 * fx;
            float w010 = a01 * ex, w011 = a01 * fx;
            float w100 = a10 * ex, w101 = a10 * fx;
            float w110 = a11 * ex, w111 = a11 * fx;

            samp.x = fmaf(w000, c000.x, fmaf(w001, c001.x, fmaf(w010, c010.x,
                     fmaf(w011, c011.x, fmaf(w100, c100.x, fmaf(w101, c101.x,
                     fmaf(w110, c110.x, w111 * c111.x)))))));
            samp.y = fmaf(w000, c000.y, fmaf(w001, c001.y, fmaf(w010, c010.y,
                     fmaf(w011, c011.y, fmaf(w100, c100.y, fmaf(w101, c101.y,
                     fmaf(w110, c110.y, w111 * c111.y)))))));
            samp.z = fmaf(w000, c000.z, fmaf(w001, c001.z, fmaf(w010, c010.z,
                     fmaf(w011, c011.z, fmaf(w100, c100.z, fmaf(w101, c101.z,
                     fmaf(w110, c110.z, w111 * c111.z)))))));
            samp.w = fmaf(w000, c000.w, fmaf(w001, c001.w, fmaf(w010, c010.w,
                     fmaf(w011, c011.w, fmaf(w100, c100.w, fmaf(w101, c101.w,
                     fmaf(w110, c110.w, w111 * c111.w)))))));
        }

        // warp-wide sum over primitives (butterfly: all lanes get the total)
        #pragma unroll
        for (int off = 16; off; off >>= 1) {
            samp.x += __shfl_xor_sync(FULL, samp.x, off);
            samp.y += __shfl_xor_sync(FULL, samp.y, off);
            samp.z += __shfl_xor_sync(FULL, samp.z, off);
            samp.w += __shfl_xor_sync(FULL, samp.w, off);
        }

        // alpha compositing (replicated on all lanes; salpha >= 0)
        float na      = fminf(alpha + samp.w * DTSTEP, 1.0f);
        float contrib = na - alpha;
        rgbx = fmaf(samp.x, contrib, rgbx);
        rgby = fmaf(samp.y, contrib, rgby);
        rgbz = fmaf(samp.z, contrib, rgbz);
        alpha = na;
        if (alpha >= 1.0f) break;  // exact: saturated => contrib=0 forever
    }

    if (lane == 0) {
        // out = concat(rayrgb[3,H,W], rayalpha[1,H,W], rayrgba[4,H,W])
        out[0 * HW + r] = rgbx;
        out[1 * HW + r] = rgby;
        out[2 * HW + r] = rgbz;
        out[3 * HW + r] = alpha;
        out[4 * HW + r] = rgbx;
        out[5 * HW + r] = rgby;
        out[6 * HW + r] = rgbz;
        out[7 * HW + r] = alpha;
    }
}

// ---------------------------------------------------------------------------
extern "C" void kernel_launch(void* const* d_in, const int* in_sizes, int n_in,
                              void* d_out, int out_size) {
    const float* raypos    = (const float*)d_in[0];
    const float* raydir    = (const float*)d_in[1];
    const float* tminmax   = (const float*)d_in[2];
    const float* primpos   = (const float*)d_in[3];
    const float* primrot   = (const float*)d_in[4];
    const float* primscale = (const float*)d_in[5];
    const float* template_ = (const float*)d_in[6];
    float* out = (float*)d_out;

    const int NREPACK = KPRIM * 4 * MM * MM * MM;  // 524288
    repack_kernel<<<(NREPACK + 255) / 256, 256>>>(template_);

    const int NTHREADS = HW * 32;                  // one warp per ray
    march_kernel<<<(NTHREADS + 255) / 256, 256>>>(
        raypos, raydir, tminmax, primpos, primrot, primscale, out);
}